// round 2
// baseline (speedup 1.0000x reference)
#include <cuda_runtime.h>
#include <cuda_bf16.h>
#include <cstdint>

// Problem constants (fixed shapes per reference)
#define CC 9
#define HH 180
#define WW 240
#define BB 8
#define NN 100000
#define TOTAL_EVENTS (BB * NN)          // 800000
#define HW (HH * WW)                    // 43200
#define CHW (CC * HW)                   // 388800
#define VOX_PER_BATCH (2 * CHW)         // 777600
#define NUM_VOX (BB * VOX_PER_BATCH)    // 6220800

// LUT over ts in [-1, 1]. LUT_N-1 = 16384 => h = 1/8192, bin offset 1/8 = 1024*h (exact grid step)
#define LUT_N 16385
#define LUT_SCALE 8192.0f
#define LUT_BIN_STEP 1024

__device__ float g_lut[LUT_N];

// ---------------------------------------------------------------------------
// Kernel 1: build LUT. One thread per sample; exact MLP evaluation.
// acc[100] register array; w2 loads via float4 (k contiguous) to keep LSU off
// the critical path; warp-uniform weight addresses broadcast from L1.
// ---------------------------------------------------------------------------
__global__ __launch_bounds__(128, 1)
void build_lut_kernel(const float* __restrict__ w1, const float* __restrict__ b1,
                      const float* __restrict__ w2, const float* __restrict__ b2,
                      const float* __restrict__ w3, const float* __restrict__ b3)
{
    int i = blockIdx.x * blockDim.x + threadIdx.x;
    if (i >= LUT_N) return;
    float ts = -1.0f + (float)i * (2.0f / (float)(LUT_N - 1));

    float acc[100];
    #pragma unroll
    for (int k = 0; k < 100; k += 4) {
        float4 bb = *reinterpret_cast<const float4*>(b2 + k);
        acc[k] = bb.x; acc[k + 1] = bb.y; acc[k + 2] = bb.z; acc[k + 3] = bb.w;
    }

    #pragma unroll 2
    for (int j = 0; j < 100; j++) {
        float h = fmaf(ts, __ldg(w1 + j), __ldg(b1 + j));
        h = (h > 0.0f) ? h : 0.1f * h;                    // LeakyReLU(0.1)
        const float4* w2row = reinterpret_cast<const float4*>(w2 + j * 100);
        #pragma unroll
        for (int k4 = 0; k4 < 25; k4++) {
            float4 w = __ldg(w2row + k4);
            acc[k4 * 4 + 0] = fmaf(h, w.x, acc[k4 * 4 + 0]);
            acc[k4 * 4 + 1] = fmaf(h, w.y, acc[k4 * 4 + 1]);
            acc[k4 * 4 + 2] = fmaf(h, w.z, acc[k4 * 4 + 2]);
            acc[k4 * 4 + 3] = fmaf(h, w.w, acc[k4 * 4 + 3]);
        }
    }

    float out = __ldg(b3);
    #pragma unroll
    for (int k = 0; k < 100; k++) {
        float h2 = (acc[k] > 0.0f) ? acc[k] : 0.1f * acc[k];
        out = fmaf(h2, __ldg(w3 + k), out);
    }
    g_lut[i] = out;
}

// ---------------------------------------------------------------------------
// Kernel 2: scatter. Grid-stride over 800k events. LUT staged in shared
// memory (random gathers -> bank-level conflicts only, no L1 sector replay).
// All 9 bins share the interpolation fraction; 9 float atomics to L2-resident
// output. Output flat index == reference's concatenated layout exactly;
// clip in the reference is provably a no-op.
// ---------------------------------------------------------------------------
__global__ void scatter_kernel(const float* __restrict__ t,
                               const int* __restrict__ x,
                               const int* __restrict__ y,
                               const int* __restrict__ p,
                               float* __restrict__ out)
{
    extern __shared__ float slut[];
    for (int i = threadIdx.x; i < LUT_N; i += blockDim.x)
        slut[i] = g_lut[i];
    __syncthreads();

    int stride = gridDim.x * blockDim.x;
    for (int e = blockIdx.x * blockDim.x + threadIdx.x; e < TOTAL_EVENTS; e += stride) {
        float tv = t[e];
        int b = e / NN;  // compiler lowers to mul-hi
        int base = x[e] + WW * y[e] + CHW * p[e] + VOX_PER_BATCH * b;

        float u = (tv + 1.0f) * LUT_SCALE;   // u in [8192, 16384)
        int   j0 = (int)u;
        float f  = u - (float)j0;

        #pragma unroll
        for (int i = 0; i < CC; i++) {
            int jd = j0 - LUT_BIN_STEP * i;  // always in [0, LUT_N-2]
            float v0 = slut[jd];
            float v1 = slut[jd + 1];
            float val = tv * fmaf(f, v1 - v0, v0);
            atomicAdd(out + base + HW * i, val);
        }
    }
}

// ---------------------------------------------------------------------------
// Launch: memset out -> build LUT -> scatter. All async on stream 0,
// graph-capturable, no allocations.
// ---------------------------------------------------------------------------
extern "C" void kernel_launch(void* const* d_in, const int* in_sizes, int n_in,
                              void* d_out, int out_size)
{
    const float* t  = (const float*)d_in[0];
    const float* w1 = (const float*)d_in[1];
    const float* b1 = (const float*)d_in[2];
    const float* w2 = (const float*)d_in[3];
    const float* b2 = (const float*)d_in[4];
    const float* w3 = (const float*)d_in[5];
    const float* b3 = (const float*)d_in[6];
    const int*   x  = (const int*)d_in[7];
    const int*   y  = (const int*)d_in[8];
    const int*   p  = (const int*)d_in[9];
    float* out = (float*)d_out;

    cudaMemsetAsync(out, 0, (size_t)out_size * sizeof(float), 0);

    build_lut_kernel<<<(LUT_N + 127) / 128, 128>>>(w1, b1, w2, b2, w3, b3);

    const int smem = LUT_N * sizeof(float);  // 65540 B
    cudaFuncSetAttribute(scatter_kernel, cudaFuncAttributeMaxDynamicSharedMemorySize, smem);
    // 3 blocks/SM * 148 SMs; 512 threads each -> 24 warps/SM for atomic latency hiding
    scatter_kernel<<<444, 512, smem>>>(t, x, y, p, out);
}

// round 3
// speedup vs baseline: 1.0547x; 1.0547x over previous
#include <cuda_runtime.h>
#include <cuda_bf16.h>
#include <cstdint>

// Problem constants (fixed shapes per reference)
#define CC 9
#define HH 180
#define WW 240
#define BB 8
#define NN 100000
#define TOTAL_EVENTS (BB * NN)          // 800000
#define HW (HH * WW)                    // 43200
#define CHW (CC * HW)                   // 388800
#define VOX_PER_BATCH (2 * CHW)         // 777600
#define NUM_VOX (BB * VOX_PER_BATCH)    // 6220800

// LUT over ts in [-1, 1]. LUT_N-1 = 2048 -> h = 1/1024; bin offset 1/8 = 128*h (exact)
#define LUT_N 2049
#define LUT_SCALE 1024.0f
#define LUT_BIN_STEP 128

#define ZBLOCKS 160                       // zero-fill blocks in prep kernel
#define LUT_THREADS (LUT_N * 4)           // 4 lanes per sample
#define LBLOCKS ((LUT_THREADS + 255) / 256)  // 33

__device__ float g_lut[LUT_N];

// ---------------------------------------------------------------------------
// Prep kernel: blocks [0, ZBLOCKS) zero the output (DRAM-write bound, ~3us);
// blocks [ZBLOCKS, ZBLOCKS+LBLOCKS) build the LUT concurrently.
// LUT build: 4 lanes per sample; each lane owns 25 of the 100 layer-1 units
// (j-split), accumulates partial layer-2 pre-activations acc[100] with
// float4 weight loads, then shfl-xor butterfly combines the 4 partials.
// Layer 3 is recomputed redundantly on all 4 lanes (static indexing keeps
// acc[] in registers); lane q==0 writes the sample.
// ---------------------------------------------------------------------------
__global__ __launch_bounds__(256)
void prep_kernel(const float* __restrict__ w1, const float* __restrict__ b1,
                 const float* __restrict__ w2, const float* __restrict__ b2,
                 const float* __restrict__ w3, const float* __restrict__ b3,
                 float* __restrict__ out)
{
    if (blockIdx.x < ZBLOCKS) {
        // ---- zero-fill path ----
        const int total4 = NUM_VOX / 4;               // 1555200 float4s
        float4 z = make_float4(0.f, 0.f, 0.f, 0.f);
        int tid = blockIdx.x * 256 + threadIdx.x;
        for (int i = tid; i < total4; i += ZBLOCKS * 256)
            reinterpret_cast<float4*>(out)[i] = z;
        return;
    }

    // ---- LUT build path ----
    int t = (blockIdx.x - ZBLOCKS) * 256 + threadIdx.x;
    int s = t >> 2;          // sample index
    int q = t & 3;           // lane role: owns j in [25q, 25q+25)
    if (s >= LUT_N) return;

    float ts = -1.0f + (float)s * (1.0f / 1024.0f);

    // Layer 1 for my 25 units
    float h[25];
    int jbase = q * 25;
    #pragma unroll
    for (int jj = 0; jj < 25; jj++) {
        float hv = fmaf(ts, __ldg(w1 + jbase + jj), __ldg(b1 + jbase + jj));
        h[jj] = (hv > 0.0f) ? hv : 0.1f * hv;
    }

    // Partial layer-2 accumulation over my j's (b2 added by lane 0 only)
    float acc[100];
    if (q == 0) {
        #pragma unroll
        for (int k = 0; k < 100; k += 4) {
            float4 bb = __ldg(reinterpret_cast<const float4*>(b2 + k));
            acc[k] = bb.x; acc[k + 1] = bb.y; acc[k + 2] = bb.z; acc[k + 3] = bb.w;
        }
    } else {
        #pragma unroll
        for (int k = 0; k < 100; k++) acc[k] = 0.0f;
    }

    for (int jj = 0; jj < 25; jj++) {
        float hv = h[jj];
        const float4* row = reinterpret_cast<const float4*>(w2 + (jbase + jj) * 100);
        #pragma unroll
        for (int k4 = 0; k4 < 25; k4++) {
            float4 w = __ldg(row + k4);
            acc[k4 * 4 + 0] = fmaf(hv, w.x, acc[k4 * 4 + 0]);
            acc[k4 * 4 + 1] = fmaf(hv, w.y, acc[k4 * 4 + 1]);
            acc[k4 * 4 + 2] = fmaf(hv, w.z, acc[k4 * 4 + 2]);
            acc[k4 * 4 + 3] = fmaf(hv, w.w, acc[k4 * 4 + 3]);
        }
    }

    // Butterfly-combine the 4 partials (the 4 lanes of one sample are
    // adjacent in the warp: lane = 4*(s%8) + q)
    #pragma unroll
    for (int k = 0; k < 100; k++) {
        acc[k] += __shfl_xor_sync(0xffffffffu, acc[k], 1);
        acc[k] += __shfl_xor_sync(0xffffffffu, acc[k], 2);
    }

    // Layer 3 (redundant on all 4 lanes; static indices keep acc in regs)
    float outv = __ldg(b3);
    #pragma unroll
    for (int k = 0; k < 100; k++) {
        float a = acc[k];
        a = (a > 0.0f) ? a : 0.1f * a;
        outv = fmaf(a, __ldg(w3 + k), outv);
    }
    if (q == 0) g_lut[s] = outv;
}

// ---------------------------------------------------------------------------
// Scatter: one wave, 4 events per thread via float4/int4 loads (1 LDG.128
// per array per 4 events). LUT stored as overlapping float2 pairs in shared
// (9 LDS.64 per event instead of 18 LDS.32). All 9 bins share the
// interpolation fraction. 9 fire-and-forget float REDG atomics per event to
// the L2-resident output. Output flat index == reference's concatenated
// layout; the reference clip is a provable no-op.
// ---------------------------------------------------------------------------
__device__ __forceinline__ void scatter_one(float tv, int xx, int yy, int pp,
                                            int bbase, const float2* slut2,
                                            float* __restrict__ out)
{
    int base = bbase + xx + WW * yy + CHW * pp;
    float u = fmaf(tv, LUT_SCALE, LUT_SCALE);     // in [1024, 2048)
    int   j0 = (int)u;
    float f  = u - (float)j0;
    #pragma unroll
    for (int i = 0; i < CC; i++) {
        float2 vv = slut2[j0 - LUT_BIN_STEP * i]; // index in [0, 2047]
        float val = tv * fmaf(f, vv.y - vv.x, vv.x);
        atomicAdd(out + base + HW * i, val);
    }
}

__global__ __launch_bounds__(512)
void scatter_kernel(const float* __restrict__ t,
                    const int* __restrict__ x,
                    const int* __restrict__ y,
                    const int* __restrict__ p,
                    float* __restrict__ out)
{
    __shared__ float2 slut2[LUT_N - 1];           // 2048 pairs, 16 KB
    for (int i = threadIdx.x; i < LUT_N - 1; i += 512)
        slut2[i] = make_float2(g_lut[i], g_lut[i + 1]);
    __syncthreads();

    int v = blockIdx.x * 512 + threadIdx.x;       // vec4 event index
    if (v >= TOTAL_EVENTS / 4) return;

    float4 t4 = __ldg(reinterpret_cast<const float4*>(t) + v);
    int4   x4 = __ldg(reinterpret_cast<const int4*>(x) + v);
    int4   y4 = __ldg(reinterpret_cast<const int4*>(y) + v);
    int4   p4 = __ldg(reinterpret_cast<const int4*>(p) + v);

    // NN/4 = 25000: all 4 events of a vec4 share the same batch
    int bbase = (v / (NN / 4)) * VOX_PER_BATCH;

    scatter_one(t4.x, x4.x, y4.x, p4.x, bbase, slut2, out);
    scatter_one(t4.y, x4.y, y4.y, p4.y, bbase, slut2, out);
    scatter_one(t4.z, x4.z, y4.z, p4.z, bbase, slut2, out);
    scatter_one(t4.w, x4.w, y4.w, p4.w, bbase, slut2, out);
}

// ---------------------------------------------------------------------------
// Launch: prep (zero + LUT, one kernel) -> scatter. Graph-capturable,
// allocation-free.
// ---------------------------------------------------------------------------
extern "C" void kernel_launch(void* const* d_in, const int* in_sizes, int n_in,
                              void* d_out, int out_size)
{
    const float* t  = (const float*)d_in[0];
    const float* w1 = (const float*)d_in[1];
    const float* b1 = (const float*)d_in[2];
    const float* w2 = (const float*)d_in[3];
    const float* b2 = (const float*)d_in[4];
    const float* w3 = (const float*)d_in[5];
    const float* b3 = (const float*)d_in[6];
    const int*   x  = (const int*)d_in[7];
    const int*   y  = (const int*)d_in[8];
    const int*   p  = (const int*)d_in[9];
    float* out = (float*)d_out;

    prep_kernel<<<ZBLOCKS + LBLOCKS, 256>>>(w1, b1, w2, b2, w3, b3, out);

    const int nvec = TOTAL_EVENTS / 4;            // 200000
    scatter_kernel<<<(nvec + 511) / 512, 512>>>(t, x, y, p, out);
}

// round 4
// speedup vs baseline: 1.3734x; 1.3021x over previous
#include <cuda_runtime.h>
#include <cuda_bf16.h>
#include <cstdint>

// Problem constants (fixed shapes per reference)
#define CC 9
#define HH 180
#define WW 240
#define BB 8
#define NN 100000
#define TOTAL_EVENTS (BB * NN)          // 800000
#define HW (HH * WW)                    // 43200
#define CHW (CC * HW)                   // 388800
#define VOX_PER_BATCH (2 * CHW)         // 777600
#define NUM_VOX (BB * VOX_PER_BATCH)    // 6220800

// LUT over ts in [-1, 1]. LUT_N-1 = 2048 -> h = 1/1024; bin offset 1/8 = 128*h (exact)
#define LUT_N 2049
#define LUT_SCALE 1024.0f
#define LUT_BIN_STEP 128

#define ZBLOCKS 148                     // zero-fill blocks (one wave, BW-bound)
#define SAMPLES_PER_BLOCK 16            // 256 threads / 16 lanes per sample
#define LUT_BLOCKS ((LUT_N + SAMPLES_PER_BLOCK - 1) / SAMPLES_PER_BLOCK)  // 129

#define KPAD 112                        // hidden dim 100 padded to 112 (4 quarters of 28, 16B-aligned)

__device__ float g_lut[LUT_N];

// ---------------------------------------------------------------------------
// Prep kernel (heterogeneous blocks, all concurrent in one wave):
//   blocks [0, ZBLOCKS): zero the 24.9MB output (DRAM-write bound, ~4us)
//   blocks [ZBLOCKS, +LUT_BLOCKS): build the LUT.
// LUT build: 16 lanes per sample. Lane (q_j, q_k) owns layer-1 units
// j in [25*q_j, +25) and layer-2 outputs k in [28*q_k, +28) (k padded with
// zeros to 112). w2 is staged zero-padded into smem once per block, so the
// inner 25x7 float4 loop is broadcast LDS. Partials combine via shfl_xor:
// (1,2) sums the j-quarters, then layer-3 partial dot, then (4,8) sums the
// k-quarters. ~750 FMA/lane vs 2500 in the previous scheme, and 129 blocks
// instead of 33 -> full-chip parallel.
// ---------------------------------------------------------------------------
__global__ __launch_bounds__(256)
void prep_kernel(const float* __restrict__ w1, const float* __restrict__ b1,
                 const float* __restrict__ w2, const float* __restrict__ b2,
                 const float* __restrict__ w3, const float* __restrict__ b3,
                 float* __restrict__ out)
{
    if (blockIdx.x < ZBLOCKS) {
        // ---- zero-fill path ----
        const int total4 = NUM_VOX / 4;               // 1555200 float4s
        float4 z = make_float4(0.f, 0.f, 0.f, 0.f);
        int tid = blockIdx.x * 256 + threadIdx.x;
        for (int i = tid; i < total4; i += ZBLOCKS * 256)
            reinterpret_cast<float4*>(out)[i] = z;
        return;
    }

    // ---- LUT build path ----
    __shared__ float s_w2[100 * KPAD];    // 44.8 KB, zero-padded columns
    __shared__ float s_b2[KPAD];
    __shared__ float s_w3[KPAD];

    for (int i = threadIdx.x; i < 100 * KPAD; i += 256) {
        int r = i / KPAD, c = i - r * KPAD;
        s_w2[i] = (c < 100) ? w2[r * 100 + c] : 0.0f;
    }
    if (threadIdx.x < KPAD) {
        s_b2[threadIdx.x] = (threadIdx.x < 100) ? b2[threadIdx.x] : 0.0f;
        s_w3[threadIdx.x] = (threadIdx.x < 100) ? w3[threadIdx.x] : 0.0f;
    }
    __syncthreads();

    int t = (blockIdx.x - ZBLOCKS) * 256 + threadIdx.x;
    int s = t >> 4;
    if (s >= LUT_N) return;
    int q_j = t & 3;
    int q_k = (t >> 2) & 3;

    float ts = -1.0f + (float)s * (1.0f / 1024.0f);

    // Layer 1: my 25 units
    float h[25];
    int jbase = q_j * 25;
    #pragma unroll
    for (int jj = 0; jj < 25; jj++) {
        float hv = fmaf(ts, __ldg(w1 + jbase + jj), __ldg(b1 + jbase + jj));
        h[jj] = (hv > 0.0f) ? hv : 0.1f * hv;
    }

    // Layer 2 partial: my 28 k's over my 25 j's
    int kbase = q_k * 28;                              // *4B in {0,112,224,336}: 16B-aligned
    float acc[28];
    #pragma unroll
    for (int kk = 0; kk < 28; kk++)
        acc[kk] = (q_j == 0) ? s_b2[kbase + kk] : 0.0f;

    #pragma unroll
    for (int jj = 0; jj < 25; jj++) {
        float hv = h[jj];
        const float4* row = reinterpret_cast<const float4*>(s_w2 + (jbase + jj) * KPAD + kbase);
        #pragma unroll
        for (int m = 0; m < 7; m++) {
            float4 w = row[m];
            acc[m * 4 + 0] = fmaf(hv, w.x, acc[m * 4 + 0]);
            acc[m * 4 + 1] = fmaf(hv, w.y, acc[m * 4 + 1]);
            acc[m * 4 + 2] = fmaf(hv, w.z, acc[m * 4 + 2]);
            acc[m * 4 + 3] = fmaf(hv, w.w, acc[m * 4 + 3]);
        }
    }

    // Combine j-quarters (lanes of one sample are contiguous: bits0-1 = q_j)
    #pragma unroll
    for (int kk = 0; kk < 28; kk++) {
        acc[kk] += __shfl_xor_sync(0xffffffffu, acc[kk], 1);
        acc[kk] += __shfl_xor_sync(0xffffffffu, acc[kk], 2);
    }

    // Layer 3 partial over my 28 k's (padded k's: acc==0 -> leaky==0, w3 pad==0)
    float part = 0.0f;
    #pragma unroll
    for (int kk = 0; kk < 28; kk++) {
        float a = acc[kk];
        a = (a > 0.0f) ? a : 0.1f * a;
        part = fmaf(a, s_w3[kbase + kk], part);
    }
    // Combine k-quarters (bits2-3 = q_k)
    part += __shfl_xor_sync(0xffffffffu, part, 4);
    part += __shfl_xor_sync(0xffffffffu, part, 8);

    if ((t & 15) == 0) g_lut[s] = part + __ldg(b3);
}

// ---------------------------------------------------------------------------
// Scatter: one vec4-event per thread (1 LDG.128 per input array per 4
// events). LUT as overlapping float2 pairs in 16KB shared (9 LDS.64/event).
// All 9 bins share the interpolation fraction; 9 fire-and-forget float REDG
// atomics per event to the L2-resident output. Output flat index ==
// reference's concatenated layout; the reference clip is a provable no-op.
// ---------------------------------------------------------------------------
__device__ __forceinline__ void scatter_one(float tv, int xx, int yy, int pp,
                                            int bbase, const float2* slut2,
                                            float* __restrict__ out)
{
    int base = bbase + xx + WW * yy + CHW * pp;
    float u = fmaf(tv, LUT_SCALE, LUT_SCALE);     // in [1024, 2048)
    int   j0 = (int)u;
    float f  = u - (float)j0;
    #pragma unroll
    for (int i = 0; i < CC; i++) {
        float2 vv = slut2[j0 - LUT_BIN_STEP * i]; // index in [0, 2047]
        float val = tv * fmaf(f, vv.y - vv.x, vv.x);
        atomicAdd(out + base + HW * i, val);
    }
}

__global__ __launch_bounds__(256)
void scatter_kernel(const float* __restrict__ t,
                    const int* __restrict__ x,
                    const int* __restrict__ y,
                    const int* __restrict__ p,
                    float* __restrict__ out)
{
    __shared__ float2 slut2[LUT_N - 1];           // 2048 pairs, 16 KB
    for (int i = threadIdx.x; i < LUT_N - 1; i += 256)
        slut2[i] = make_float2(g_lut[i], g_lut[i + 1]);
    __syncthreads();

    int v = blockIdx.x * 256 + threadIdx.x;       // vec4 event index
    if (v >= TOTAL_EVENTS / 4) return;

    float4 t4 = __ldg(reinterpret_cast<const float4*>(t) + v);
    int4   x4 = __ldg(reinterpret_cast<const int4*>(x) + v);
    int4   y4 = __ldg(reinterpret_cast<const int4*>(y) + v);
    int4   p4 = __ldg(reinterpret_cast<const int4*>(p) + v);

    // NN/4 = 25000: all 4 events of a vec4 share the same batch
    int bbase = (v / (NN / 4)) * VOX_PER_BATCH;

    scatter_one(t4.x, x4.x, y4.x, p4.x, bbase, slut2, out);
    scatter_one(t4.y, x4.y, y4.y, p4.y, bbase, slut2, out);
    scatter_one(t4.z, x4.z, y4.z, p4.z, bbase, slut2, out);
    scatter_one(t4.w, x4.w, y4.w, p4.w, bbase, slut2, out);
}

// ---------------------------------------------------------------------------
// Launch: prep (zero + LUT, one kernel) -> scatter. Graph-capturable,
// allocation-free.
// ---------------------------------------------------------------------------
extern "C" void kernel_launch(void* const* d_in, const int* in_sizes, int n_in,
                              void* d_out, int out_size)
{
    const float* t  = (const float*)d_in[0];
    const float* w1 = (const float*)d_in[1];
    const float* b1 = (const float*)d_in[2];
    const float* w2 = (const float*)d_in[3];
    const float* b2 = (const float*)d_in[4];
    const float* w3 = (const float*)d_in[5];
    const float* b3 = (const float*)d_in[6];
    const int*   x  = (const int*)d_in[7];
    const int*   y  = (const int*)d_in[8];
    const int*   p  = (const int*)d_in[9];
    float* out = (float*)d_out;

    prep_kernel<<<ZBLOCKS + LUT_BLOCKS, 256>>>(w1, b1, w2, b2, w3, b3, out);

    const int nvec = TOTAL_EVENTS / 4;            // 200000
    scatter_kernel<<<(nvec + 255) / 256, 256>>>(t, x, y, p, out);
}

// round 6
// speedup vs baseline: 1.9516x; 1.4210x over previous
#include <cuda_runtime.h>
#include <cuda_bf16.h>
#include <cstdint>

// Problem constants (fixed shapes per reference)
#define CC 9
#define HH 180
#define WW 240
#define BB 8
#define NN 100000
#define TOTAL_EVENTS (BB * NN)          // 800000
#define HW (HH * WW)                    // 43200
#define CHW (CC * HW)                   // 388800
#define VOX_PER_BATCH (2 * CHW)         // 777600
#define NUM_VOX (BB * VOX_PER_BATCH)    // 6220800

// Scratch accumulator: layout (b, p, y, x, bin) with bin padded 9 -> 12 floats
// (48B/cell, 16B aligned) so the 9 bins of one event are 2x red.v4 + 1x red.f32.
#define NCELLS (BB * 2 * HW)            // 691200
#define CELL_F 12
__device__ float4 g_vox_alt4[NCELLS * CELL_F / 4];   // 33.2 MB, 16B-aligned

// LUT over ts in [-1, 1]. LUT_N-1 = 2048 -> h = 1/1024; bin offset 1/8 = 128*h (exact)
#define LUT_N 2049
#define LUT_SCALE 1024.0f
#define LUT_BIN_STEP 128

#define ZBLOCKS 148                     // zero-fill blocks (one wave, BW-bound)
#define SAMPLES_PER_BLOCK 16            // 256 threads / 16 lanes per sample
#define LUT_BLOCKS ((LUT_N + SAMPLES_PER_BLOCK - 1) / SAMPLES_PER_BLOCK)  // 129

#define KPAD 112                        // hidden dim padded to 112 (4 quarters of 28)

__device__ float g_lut[LUT_N];

// ---------------------------------------------------------------------------
// Prep kernel (heterogeneous blocks, one wave):
//   blocks [0, ZBLOCKS): zero the 33.2MB scratch accumulator (d_out needs no
//   zeroing: the transpose kernel overwrites every element).
//   blocks [ZBLOCKS, +LUT_BLOCKS): build the LUT (16 lanes/sample, w2 staged
//   in smem, shfl_xor combines).
// ---------------------------------------------------------------------------
__global__ __launch_bounds__(256)
void prep_kernel(const float* __restrict__ w1, const float* __restrict__ b1,
                 const float* __restrict__ w2, const float* __restrict__ b2,
                 const float* __restrict__ w3, const float* __restrict__ b3)
{
    if (blockIdx.x < ZBLOCKS) {
        const int total4 = NCELLS * CELL_F / 4;       // 2,073,600 float4s
        float4 z = make_float4(0.f, 0.f, 0.f, 0.f);
        int tid = blockIdx.x * 256 + threadIdx.x;
        for (int i = tid; i < total4; i += ZBLOCKS * 256)
            g_vox_alt4[i] = z;
        return;
    }

    // ---- LUT build path ----
    __shared__ float s_w2[100 * KPAD];    // 44.8 KB, zero-padded columns
    __shared__ float s_b2[KPAD];
    __shared__ float s_w3[KPAD];

    for (int i = threadIdx.x; i < 100 * KPAD; i += 256) {
        int r = i / KPAD, c = i - r * KPAD;
        s_w2[i] = (c < 100) ? w2[r * 100 + c] : 0.0f;
    }
    if (threadIdx.x < KPAD) {
        s_b2[threadIdx.x] = (threadIdx.x < 100) ? b2[threadIdx.x] : 0.0f;
        s_w3[threadIdx.x] = (threadIdx.x < 100) ? w3[threadIdx.x] : 0.0f;
    }
    __syncthreads();

    int t = (blockIdx.x - ZBLOCKS) * 256 + threadIdx.x;
    int s = t >> 4;
    if (s >= LUT_N) return;
    int q_j = t & 3;
    int q_k = (t >> 2) & 3;

    float ts = -1.0f + (float)s * (1.0f / 1024.0f);

    float h[25];
    int jbase = q_j * 25;
    #pragma unroll
    for (int jj = 0; jj < 25; jj++) {
        float hv = fmaf(ts, __ldg(w1 + jbase + jj), __ldg(b1 + jbase + jj));
        h[jj] = (hv > 0.0f) ? hv : 0.1f * hv;
    }

    int kbase = q_k * 28;
    float acc[28];
    #pragma unroll
    for (int kk = 0; kk < 28; kk++)
        acc[kk] = (q_j == 0) ? s_b2[kbase + kk] : 0.0f;

    #pragma unroll
    for (int jj = 0; jj < 25; jj++) {
        float hv = h[jj];
        const float4* row = reinterpret_cast<const float4*>(s_w2 + (jbase + jj) * KPAD + kbase);
        #pragma unroll
        for (int m = 0; m < 7; m++) {
            float4 w = row[m];
            acc[m * 4 + 0] = fmaf(hv, w.x, acc[m * 4 + 0]);
            acc[m * 4 + 1] = fmaf(hv, w.y, acc[m * 4 + 1]);
            acc[m * 4 + 2] = fmaf(hv, w.z, acc[m * 4 + 2]);
            acc[m * 4 + 3] = fmaf(hv, w.w, acc[m * 4 + 3]);
        }
    }

    #pragma unroll
    for (int kk = 0; kk < 28; kk++) {
        acc[kk] += __shfl_xor_sync(0xffffffffu, acc[kk], 1);
        acc[kk] += __shfl_xor_sync(0xffffffffu, acc[kk], 2);
    }

    float part = 0.0f;
    #pragma unroll
    for (int kk = 0; kk < 28; kk++) {
        float a = acc[kk];
        a = (a > 0.0f) ? a : 0.1f * a;
        part = fmaf(a, s_w3[kbase + kk], part);
    }
    part += __shfl_xor_sync(0xffffffffu, part, 4);
    part += __shfl_xor_sync(0xffffffffu, part, 8);

    if ((t & 15) == 0) g_lut[s] = part + __ldg(b3);
}

// ---------------------------------------------------------------------------
// Scatter: accumulate into (b,p,y,x,bin) scratch. The 9 bin-values of one
// event live in one 48B cell -> 2x red.global.add.v4.f32 + 1x red scalar
// (3 L2 sectors per event instead of 9 separate 172KB-strided lines).
// LUT as overlapping float2 pairs in 16KB smem; all 9 bins share the
// interpolation fraction.
// ---------------------------------------------------------------------------
__device__ __forceinline__ void scatter_one(float tv, int xx, int yy, int pp,
                                            int bp2, const float2* slut2)
{
    int cell = (bp2 + pp) * HW + yy * WW + xx;
    float* cp = reinterpret_cast<float*>(g_vox_alt4) + cell * CELL_F;

    float u = fmaf(tv, LUT_SCALE, LUT_SCALE);     // in [1024, 2048)
    int   j0 = (int)u;
    float f  = u - (float)j0;

    float v[9];
    #pragma unroll
    for (int i = 0; i < CC; i++) {
        float2 vv = slut2[j0 - LUT_BIN_STEP * i]; // index in [0, 2047]
        v[i] = tv * fmaf(f, vv.y - vv.x, vv.x);
    }

    asm volatile("red.global.add.v4.f32 [%0], {%1, %2, %3, %4};"
                 :: "l"(cp), "f"(v[0]), "f"(v[1]), "f"(v[2]), "f"(v[3]) : "memory");
    asm volatile("red.global.add.v4.f32 [%0], {%1, %2, %3, %4};"
                 :: "l"(cp + 4), "f"(v[4]), "f"(v[5]), "f"(v[6]), "f"(v[7]) : "memory");
    asm volatile("red.global.add.f32 [%0], %1;"
                 :: "l"(cp + 8), "f"(v[8]) : "memory");
}

__global__ __launch_bounds__(256)
void scatter_kernel(const float* __restrict__ t,
                    const int* __restrict__ x,
                    const int* __restrict__ y,
                    const int* __restrict__ p)
{
    __shared__ float2 slut2[LUT_N - 1];           // 2048 pairs, 16 KB
    for (int i = threadIdx.x; i < LUT_N - 1; i += 256)
        slut2[i] = make_float2(g_lut[i], g_lut[i + 1]);
    __syncthreads();

    int v = blockIdx.x * 256 + threadIdx.x;       // vec4 event index
    if (v >= TOTAL_EVENTS / 4) return;

    float4 t4 = __ldg(reinterpret_cast<const float4*>(t) + v);
    int4   x4 = __ldg(reinterpret_cast<const int4*>(x) + v);
    int4   y4 = __ldg(reinterpret_cast<const int4*>(y) + v);
    int4   p4 = __ldg(reinterpret_cast<const int4*>(p) + v);

    // NN/4 = 25000: all 4 events of a vec4 share the same batch
    int bp2 = (v / (NN / 4)) * 2;                 // b*2

    scatter_one(t4.x, x4.x, y4.x, p4.x, bp2, slut2);
    scatter_one(t4.y, x4.y, y4.y, p4.y, bp2, slut2);
    scatter_one(t4.z, x4.z, y4.z, p4.z, bp2, slut2);
    scatter_one(t4.w, x4.w, y4.w, p4.w, bp2, slut2);
}

// ---------------------------------------------------------------------------
// Transpose: (b,p,y,x,bin) scratch -> (b, p*C+bin, y, x) output. One thread
// per cell: 3 LDG.128 (contiguous, L2-resident) + 9 coalesced STG.32 (for
// fixed bin, consecutive threads hit consecutive addresses). Overwrites
// every output element -> no output zeroing anywhere.
// ---------------------------------------------------------------------------
__global__ __launch_bounds__(256)
void transpose_kernel(float* __restrict__ out)
{
    int c = blockIdx.x * 256 + threadIdx.x;       // cell = (b*2+p)*HW + y*W + x
    if (c >= NCELLS) return;

    int bp = c / HW;
    int yx = c - bp * HW;
    // out index for bin i: b*2CHW + p*CHW + i*HW + yx == bp*CHW + i*HW + yx
    int obase = bp * CHW + yx;

    const float4* src = g_vox_alt4 + c * 3;
    float4 a0 = src[0];
    float4 a1 = src[1];
    float4 a2 = src[2];

    out[obase + 0 * HW] = a0.x;
    out[obase + 1 * HW] = a0.y;
    out[obase + 2 * HW] = a0.z;
    out[obase + 3 * HW] = a0.w;
    out[obase + 4 * HW] = a1.x;
    out[obase + 5 * HW] = a1.y;
    out[obase + 6 * HW] = a1.z;
    out[obase + 7 * HW] = a1.w;
    out[obase + 8 * HW] = a2.x;
}

// ---------------------------------------------------------------------------
// Launch: prep (zero scratch + LUT) -> scatter -> transpose. Graph-capturable,
// allocation-free (scratch is a __device__ global).
// ---------------------------------------------------------------------------
extern "C" void kernel_launch(void* const* d_in, const int* in_sizes, int n_in,
                              void* d_out, int out_size)
{
    const float* t  = (const float*)d_in[0];
    const float* w1 = (const float*)d_in[1];
    const float* b1 = (const float*)d_in[2];
    const float* w2 = (const float*)d_in[3];
    const float* b2 = (const float*)d_in[4];
    const float* w3 = (const float*)d_in[5];
    const float* b3 = (const float*)d_in[6];
    const int*   x  = (const int*)d_in[7];
    const int*   y  = (const int*)d_in[8];
    const int*   p  = (const int*)d_in[9];
    float* out = (float*)d_out;

    prep_kernel<<<ZBLOCKS + LUT_BLOCKS, 256>>>(w1, b1, w2, b2, w3, b3);

    const int nvec = TOTAL_EVENTS / 4;            // 200000
    scatter_kernel<<<(nvec + 255) / 256, 256>>>(t, x, y, p);

    transpose_kernel<<<(NCELLS + 255) / 256, 256>>>(out);
}